// round 9
// baseline (speedup 1.0000x reference)
#include <cuda_runtime.h>
#include <cstddef>

// Problem shape (fixed by reference): x[1, 32, 256, 256, 8] float32
constexpr int D_ = 32;
constexpr int H_ = 256;
constexpr int W_ = 256;
constexpr int C_ = 8;
constexpr int TW = 32;   // w-strip per thread

// ---------------------------------------------------------------------------
// Compare-exchange.
// Hard: 2x FMNMX (alu pipe), depth 1.
// Soft (sum trick): s = a+b (FFMA imm-form, rt1); mn = min(a,b) (FMNMX);
//                   mx = s - mn (FFMA imm-form, rt1).  1 alu + 2 cheap fma.
// ---------------------------------------------------------------------------
template <bool SOFT>
__device__ __forceinline__ void ce(float a, float b, float& mn, float& mx) {
    if constexpr (SOFT) {
        float s;
        asm("fma.rn.f32 %0, %1, 0f3F800000, %2;" : "=f"(s) : "f"(a), "f"(b));   // s = a + b
        mn = fminf(a, b);
        asm("fma.rn.f32 %0, %1, 0fBF800000, %2;" : "=f"(mx) : "f"(mn), "f"(s)); // mx = s - mn
    } else {
        mn = fminf(a, b);
        mx = fmaxf(a, b);
    }
}

// ---------------------------------------------------------------------------
// Generalized Batcher odd-even merge of two sorted lists (arbitrary M, N).
// Unused outputs are dead-code eliminated (exploited for truncated selection).
// ---------------------------------------------------------------------------
template <int M, int N, bool SOFT>
__device__ __forceinline__ void omerge(const float* A, const float* B, float* R) {
    if constexpr (M == 0) {
#pragma unroll
        for (int i = 0; i < N; ++i) R[i] = B[i];
    } else if constexpr (N == 0) {
#pragma unroll
        for (int i = 0; i < M; ++i) R[i] = A[i];
    } else if constexpr (M == 1 && N == 1) {
        ce<SOFT>(A[0], B[0], R[0], R[1]);
    } else {
        constexpr int ME = (M + 1) / 2, MO = M / 2;
        constexpr int NE = (N + 1) / 2, NO = N / 2;
        float Ae[ME], Be[NE];
        float Ao[MO > 0 ? MO : 1], Bo[NO > 0 ? NO : 1];
#pragma unroll
        for (int i = 0; i < ME; ++i) Ae[i] = A[2 * i];
#pragma unroll
        for (int i = 0; i < MO; ++i) Ao[i] = A[2 * i + 1];
#pragma unroll
        for (int i = 0; i < NE; ++i) Be[i] = B[2 * i];
#pragma unroll
        for (int i = 0; i < NO; ++i) Bo[i] = B[2 * i + 1];

        constexpr int ES = ME + NE, OS = MO + NO;
        float E[ES], O[OS > 0 ? OS : 1];
        omerge<ME, NE, SOFT>(Ae, Be, E);
        omerge<MO, NO, SOFT>(Ao, Bo, O);

        R[0] = E[0];
#pragma unroll
        for (int i = 0; i < OS; ++i) {
            if (i + 1 < ES) {
                ce<SOFT>(O[i], E[i + 1], R[2 * i + 1], R[2 * i + 2]);
            } else {
                R[2 * i + 1] = O[i];
            }
        }
        if constexpr (ES == OS + 2) R[M + N - 1] = E[ES - 1];
    }
}

template <int N, bool SOFT>
__device__ __forceinline__ void nsort(float* A) {
    if constexpr (N > 1) {
        constexpr int L = N / 2;
        nsort<L, SOFT>(A);
        nsort<N - L, SOFT>(A + L);
        float R[N];
        omerge<L, N - L, SOFT>(A, A + L, R);
#pragma unroll
        for (int i = 0; i < N; ++i) A[i] = R[i];
    }
}

// jnp.pad mode="reflect": -1 -> 1, n -> n-2
__device__ __forceinline__ int refl(int i, int n) {
    i = (i < 0) ? -i : i;
    i = (i >= n) ? (2 * n - 2 - i) : i;
    return i;
}

// ---------------------------------------------------------------------------
// Column loaders. Fast: single walking pointer, row offsets are SASS LDG
// immediates (i*8192B), pointer advances by one column (32B) per call.
// Edge: 5 reflected row pointers + per-call w reflection.
// ---------------------------------------------------------------------------
struct FastLd {
    const float* p;
    __device__ __forceinline__ void operator()(float (&Cv)[5]) {
#pragma unroll
        for (int i = 0; i < 5; ++i) Cv[i] = __ldg(p + i * (W_ * C_));
        p += C_;
    }
};

struct EdgeLd {
    const float* rp[5];
    int wc;
    __device__ __forceinline__ void operator()(float (&Cv)[5]) {
        const int off = refl(wc, W_) * C_;
#pragma unroll
        for (int i = 0; i < 5; ++i) Cv[i] = __ldg(rp[i] + off);
        ++wc;
    }
};

// One sliding step producing the median at output column w.
//   PL = P_{w-2}, PR = P_w (sorted 10s), Cold = sorted col_{w+1}.
//   Loads col_{w+2} -> Cnew, emits PO = P_{w+1} (reused at w+1 and w+3).
// Median(25) = rank-13 of PL u PR u col_{w+2}: only ranks 8..13 of
// merge(PL,PR) can be the median; final rank-6 of 6 u 5 via the two-list
// minimax identity. Soft CEs in sort5 + pair merge (dual-output CEs);
// truncated merge and minimax stay hard.
template <class LD>
__device__ __forceinline__ float med_step(
    LD& ld,
    const float (&PL)[10], const float (&PR)[10], float (&PO)[10],
    const float (&Cold)[5], float (&Cnew)[5]) {
    ld(Cnew);
    nsort<5, true>(Cnew);
    omerge<5, 5, true>(Cold, Cnew, PO);

    float Z[20];
    omerge<10, 10, false>(PL, PR, Z);     // truncated: only Z[7..12] survive DCE

    float m;
    m = fminf(fmaxf(Z[7],  Cnew[4]),
        fminf(fmaxf(Z[8],  Cnew[3]),
        fminf(fmaxf(Z[9],  Cnew[2]),
        fminf(fmaxf(Z[10], Cnew[1]),
        fminf(fmaxf(Z[11], Cnew[0]), Z[12])))));
    return m;
}

template <class LD>
__device__ __forceinline__ void run_strip(LD& ld, float* out) {
    // Pipeline state: ring of 4 pair-merges + 2 alternating sorted columns.
    float PA[10], PB[10], PC[10], PD[10];
    float Ca[5], Cb[5];
    {
        float c0[5], c1[5], c2[5];
        ld(c0); nsort<5, true>(c0);
        ld(c1); nsort<5, true>(c1);
        ld(c2); nsort<5, true>(c2);
        ld(Ca); nsort<5, true>(Ca);
        omerge<5, 5, true>(c0, c1, PA);  // P_{t0-2}
        omerge<5, 5, true>(c1, c2, PB);  // P_{t0-1}
        omerge<5, 5, true>(c2, Ca, PC);  // P_{t0}
    }

    // 4-phase ring rotation: at output w the roles are
    //   (PL, PR, PO) = (P_{w-2}, P_w, P_{w+1}); Cold = col_{w+1}.
#pragma unroll 1
    for (int w = 0; w < TW; w += 4) {
        out[(w + 0) * C_] = med_step(ld, PA, PC, PD, Ca, Cb);
        out[(w + 1) * C_] = med_step(ld, PB, PD, PA, Cb, Ca);
        out[(w + 2) * C_] = med_step(ld, PC, PA, PB, Ca, Cb);
        out[(w + 3) * C_] = med_step(ld, PD, PB, PC, Cb, Ca);
    }
}

__global__ void __launch_bounds__(64, 16)
median5x5_kernel(const float* __restrict__ x, float* __restrict__ y) {
    const int bid = blockIdx.x;
    const int wt = bid & 7;          // 8 w-tiles of 32
    const int ht = (bid >> 3) & 31;  // 32 h-tiles of 8
    const int d  = bid >> 8;         // 32 depth slices
    const int c  = threadIdx.x & 7;  // channel (contiguous for coalescing)
    const int h  = ht * 8 + (threadIdx.x >> 3);
    const int t0 = wt * TW;

    float* out = y + (((size_t)d * H_ + h) * W_ + t0) * C_ + c;

    // Fast path: no h reflection (ht 1..30 -> h in [8,247], needs [2,253])
    // and no w reflection (wt 1..6 -> wc in [30,225] subset of [0,255]).
    const bool fast = (wt != 0) & (wt != 7) & (ht != 0) & (ht != 31);
    if (fast) {
        FastLd ld;
        ld.p = x + (size_t)d * (H_ * W_ * C_) + (size_t)(h - 2) * (W_ * C_)
                 + (t0 - 2) * C_ + c;
        run_strip(ld, out);
    } else {
        EdgeLd ld;
        const float* base = x + (size_t)d * (H_ * W_ * C_) + c;
#pragma unroll
        for (int i = 0; i < 5; ++i) {
            const int rh = refl(h - 2 + i, H_);
            ld.rp[i] = base + (size_t)rh * (W_ * C_);
        }
        ld.wc = t0 - 2;
        run_strip(ld, out);
    }
}

extern "C" void kernel_launch(void* const* d_in, const int* in_sizes, int n_in,
                              void* d_out, int out_size) {
    const float* x = (const float*)d_in[0];
    float* y = (float*)d_out;
    // grid: 32 d * 32 h-tiles * 8 w-tiles = 8192 blocks of 64 threads
    median5x5_kernel<<<8192, 64>>>(x, y);
}